// round 8
// baseline (speedup 1.0000x reference)
#include <cuda_runtime.h>
#include <stdint.h>

// SkipGramNS: out[i] = dot(cxt_weight[ctx_idx[i]], tgt_weight[tgt_idx[i]])
// N=1e6, D=128, V=1e5.
//
// R8 model: binder is the L1tex wavefront queue. Vector LDG.128 gathers
// produce 4 within-LDG replay wavefronts (~2.07 cyc/wf); scalar LDG.32 with
// all 32 lanes inside ONE 128B line produces 1 wavefront per LDG serviced at
// ~1.0 cyc/wf. Same wavefront count per pair (8), ~2x service rate.
// Geometry: one warp per pair; instruction k loads row[32k + lane];
// 8 independent single-line LDGs per pair (MLP=8); 5-shuffle reduce.

__global__ void __launch_bounds__(256)
skipgram_dot_kernel(const int* __restrict__ ctx_idx,
                    const int* __restrict__ tgt_idx,
                    const float* __restrict__ cxt_w,
                    const float* __restrict__ tgt_w,
                    float* __restrict__ out,
                    int n)
{
    const int warp_id = (blockIdx.x * blockDim.x + threadIdx.x) >> 5;
    const int lane    = threadIdx.x & 31;
    if (warp_id >= n) return;

    const long long c = (long long)__ldg(&ctx_idx[warp_id]);
    const long long t = (long long)__ldg(&tgt_idx[warp_id]);

    const float* __restrict__ cv = cxt_w + c * 128 + lane;
    const float* __restrict__ tv = tgt_w + t * 128 + lane;

    // 8 independent single-128B-line loads (1 wavefront each)
    const float a0 = __ldg(cv);
    const float a1 = __ldg(cv + 32);
    const float a2 = __ldg(cv + 64);
    const float a3 = __ldg(cv + 96);
    const float b0 = __ldg(tv);
    const float b1 = __ldg(tv + 32);
    const float b2 = __ldg(tv + 64);
    const float b3 = __ldg(tv + 96);

    float s = a0 * b0;
    s = fmaf(a1, b1, s);
    s = fmaf(a2, b2, s);
    s = fmaf(a3, b3, s);

    // full-warp butterfly reduction
    #pragma unroll
    for (int off = 16; off > 0; off >>= 1)
        s += __shfl_xor_sync(0xFFFFFFFFu, s, off);

    if (lane == 0)
        __stcs(&out[warp_id], s);
}

extern "C" void kernel_launch(void* const* d_in, const int* in_sizes, int n_in,
                              void* d_out, int out_size)
{
    const int*   ctx_idx = (const int*)d_in[0];
    const int*   tgt_idx = (const int*)d_in[1];
    const float* cxt_w   = (const float*)d_in[2];
    const float* tgt_w   = (const float*)d_in[3];
    float*       out     = (float*)d_out;

    const int n = in_sizes[0];              // 1,000,000 pairs
    const int threads = 256;                // 8 warps/block, 8 pairs/block
    const int warps_per_block = threads / 32;
    const int blocks = (n + warps_per_block - 1) / warps_per_block;

    skipgram_dot_kernel<<<blocks, threads>>>(ctx_idx, tgt_idx, cxt_w, tgt_w, out, n);
}

// round 9
// speedup vs baseline: 1.6947x; 1.6947x over previous
#include <cuda_runtime.h>
#include <stdint.h>

// SkipGramNS: out[i] = dot(cxt_weight[ctx_idx[i]], tgt_weight[tgt_idx[i]])
// N=1e6, D=128, V=1e5.
//
// R9 = R3's amortization (4 pairs/warp, ~30cyc fixed warp cost spread out)
//    + R8's load shape (scalar LDG.32, all 32 lanes in ONE 128B line ->
//      1 wavefront/LDG at the ~1.0 cyc/wf cross-LDG rate, vs ~2.07 cyc/wf
//      for within-LDG.128 replays).
// Per warp: 2x int4 index loads + 32 independent single-line LDG.32,
// 16 FMAs/lane, 11-shuffle grouped reduction, 4 stores.

__global__ void __launch_bounds__(256)
skipgram_dot_kernel(const int* __restrict__ ctx_idx,
                    const int* __restrict__ tgt_idx,
                    const float* __restrict__ cxt_w,
                    const float* __restrict__ tgt_w,
                    float* __restrict__ out,
                    int n)
{
    const int warp_id = (blockIdx.x * blockDim.x + threadIdx.x) >> 5;
    const int lane    = threadIdx.x & 31;
    const int base    = warp_id * 4;
    if (base >= n) return;

    // 8 indices for the warp's 4 pairs (n % 4 == 0 for N=1e6; guard anyway)
    int4 ci, ti;
    if (base + 3 < n) {
        ci = __ldg(reinterpret_cast<const int4*>(ctx_idx + base));
        ti = __ldg(reinterpret_cast<const int4*>(tgt_idx + base));
    } else {
        ci.x = __ldg(&ctx_idx[base]);
        ci.y = (base + 1 < n) ? __ldg(&ctx_idx[base + 1]) : ci.x;
        ci.z = (base + 2 < n) ? __ldg(&ctx_idx[base + 2]) : ci.x;
        ci.w = ci.x;
        ti.x = __ldg(&tgt_idx[base]);
        ti.y = (base + 1 < n) ? __ldg(&tgt_idx[base + 1]) : ti.x;
        ti.z = (base + 2 < n) ? __ldg(&tgt_idx[base + 2]) : ti.x;
        ti.w = ti.x;
    }

    const float* __restrict__ c0 = cxt_w + (long long)ci.x * 128 + lane;
    const float* __restrict__ c1 = cxt_w + (long long)ci.y * 128 + lane;
    const float* __restrict__ c2 = cxt_w + (long long)ci.z * 128 + lane;
    const float* __restrict__ c3 = cxt_w + (long long)ci.w * 128 + lane;
    const float* __restrict__ t0 = tgt_w + (long long)ti.x * 128 + lane;
    const float* __restrict__ t1 = tgt_w + (long long)ti.y * 128 + lane;
    const float* __restrict__ t2 = tgt_w + (long long)ti.z * 128 + lane;
    const float* __restrict__ t3 = tgt_w + (long long)ti.w * 128 + lane;

    // 32 independent single-128B-line loads
    float a0[4], a1[4], a2[4], a3[4], b0[4], b1[4], b2[4], b3[4];
    #pragma unroll
    for (int k = 0; k < 4; k++) a0[k] = __ldg(c0 + 32 * k);
    #pragma unroll
    for (int k = 0; k < 4; k++) b0[k] = __ldg(t0 + 32 * k);
    #pragma unroll
    for (int k = 0; k < 4; k++) a1[k] = __ldg(c1 + 32 * k);
    #pragma unroll
    for (int k = 0; k < 4; k++) b1[k] = __ldg(t1 + 32 * k);
    #pragma unroll
    for (int k = 0; k < 4; k++) a2[k] = __ldg(c2 + 32 * k);
    #pragma unroll
    for (int k = 0; k < 4; k++) b2[k] = __ldg(t2 + 32 * k);
    #pragma unroll
    for (int k = 0; k < 4; k++) a3[k] = __ldg(c3 + 32 * k);
    #pragma unroll
    for (int k = 0; k < 4; k++) b3[k] = __ldg(t3 + 32 * k);

    float s0 = 0.f, s1 = 0.f, s2 = 0.f, s3 = 0.f;
    #pragma unroll
    for (int k = 0; k < 4; k++) s0 = fmaf(a0[k], b0[k], s0);
    #pragma unroll
    for (int k = 0; k < 4; k++) s1 = fmaf(a1[k], b1[k], s1);
    #pragma unroll
    for (int k = 0; k < 4; k++) s2 = fmaf(a2[k], b2[k], s2);
    #pragma unroll
    for (int k = 0; k < 4; k++) s3 = fmaf(a3[k], b3[k], s3);

    // grouped reduction: after xor16+xor8, s_p(lane) holds the sum of s_p
    // over the 4-lane coset {lane, lane^8, lane^16, lane^24}; select the
    // group's own pair, then fold xor4/2/1 within the 8-lane group.
    s0 += __shfl_xor_sync(0xFFFFFFFFu, s0, 16);
    s1 += __shfl_xor_sync(0xFFFFFFFFu, s1, 16);
    s2 += __shfl_xor_sync(0xFFFFFFFFu, s2, 16);
    s3 += __shfl_xor_sync(0xFFFFFFFFu, s3, 16);
    s0 += __shfl_xor_sync(0xFFFFFFFFu, s0, 8);
    s1 += __shfl_xor_sync(0xFFFFFFFFu, s1, 8);
    s2 += __shfl_xor_sync(0xFFFFFFFFu, s2, 8);
    s3 += __shfl_xor_sync(0xFFFFFFFFu, s3, 8);

    const int group = lane >> 3;           // 0..3
    float v = (group == 0) ? s0 : (group == 1) ? s1 : (group == 2) ? s2 : s3;
    v += __shfl_xor_sync(0xFFFFFFFFu, v, 4);
    v += __shfl_xor_sync(0xFFFFFFFFu, v, 2);
    v += __shfl_xor_sync(0xFFFFFFFFu, v, 1);

    const int pair = base + group;
    if ((lane & 7) == 0 && pair < n)
        __stcs(&out[pair], v);
}

extern "C" void kernel_launch(void* const* d_in, const int* in_sizes, int n_in,
                              void* d_out, int out_size)
{
    const int*   ctx_idx = (const int*)d_in[0];
    const int*   tgt_idx = (const int*)d_in[1];
    const float* cxt_w   = (const float*)d_in[2];
    const float* tgt_w   = (const float*)d_in[3];
    float*       out     = (float*)d_out;

    const int n = in_sizes[0];              // 1,000,000 pairs
    const int threads = 256;                // 8 warps/block, 32 pairs/block
    const int pairs_per_block = (threads / 32) * 4;
    const int blocks = (n + pairs_per_block - 1) / pairs_per_block;

    skipgram_dot_kernel<<<blocks, threads>>>(ctx_idx, tgt_idx, cxt_w, tgt_w, out, n);
}